// round 9
// baseline (speedup 1.0000x reference)
#include <cuda_runtime.h>
#include <cuda_bf16.h>
#include <cstdint>

// Problem constants (fixed by the dataset)
#define B_  4
#define T_  2048
#define NH_ 8
#define N_  64
#define D_  128
#define C_  128          // chunk length
#define NC_ 16           // T_/C_
#define OUT_ELEMS (B_*T_*NH_*D_)   // 8,388,608
#define ST_ELEMS  (B_*NH_*N_*D_)   // 262,144

// Scratch:
//  g_dS        : per-chunk delta-state, layout [bh*16+k][d][n] fp32
//  g_sph/g_spl : prefix state (state + sum_{j<k} dS_j), bf16 hi/lo planes, [blk][d][n]
__device__ float         g_dS [(size_t)512*8192];
__device__ __nv_bfloat16 g_sph[(size_t)512*8192];
__device__ __nv_bfloat16 g_spl[(size_t)512*8192];

// ---------------------------------------------------------------------------
// helpers
// ---------------------------------------------------------------------------
__device__ __forceinline__ uint32_t smem_u32(const void* p) {
    uint32_t a;
    asm("{ .reg .u64 t; cvta.to.shared.u64 t, %1; cvt.u32.u64 %0, t; }"
        : "=r"(a) : "l"(p));
    return a;
}
__device__ __forceinline__ void ldmx4(uint32_t* r, uint32_t a) {
    asm volatile("ldmatrix.sync.aligned.m8n8.x4.shared.b16 {%0,%1,%2,%3}, [%4];"
                 : "=r"(r[0]), "=r"(r[1]), "=r"(r[2]), "=r"(r[3]) : "r"(a));
}
__device__ __forceinline__ void ldmx4t(uint32_t* r, uint32_t a) {
    asm volatile("ldmatrix.sync.aligned.m8n8.x4.trans.shared.b16 {%0,%1,%2,%3}, [%4];"
                 : "=r"(r[0]), "=r"(r[1]), "=r"(r[2]), "=r"(r[3]) : "r"(a));
}
// D += A * B, m16n8k16, row.col, bf16 in / fp32 accum
__device__ __forceinline__ void mma(float* d, const uint32_t* a, const uint32_t* b) {
    asm volatile("mma.sync.aligned.m16n8k16.row.col.f32.bf16.bf16.f32 "
                 "{%0,%1,%2,%3}, {%4,%5,%6,%7}, {%8,%9}, {%0,%1,%2,%3};"
                 : "+f"(d[0]), "+f"(d[1]), "+f"(d[2]), "+f"(d[3])
                 : "r"(a[0]), "r"(a[1]), "r"(a[2]), "r"(a[3]),
                   "r"(b[0]), "r"(b[1]));
}
// fp32 pair -> packed bf16x2 hi plane + residual lo plane (a in low half).
__device__ __forceinline__ void split2(float a, float b, uint32_t& hi, uint32_t& lo) {
    uint32_t h;
    asm("cvt.rn.bf16x2.f32 %0, %1, %2;" : "=r"(h) : "f"(b), "f"(a));
    float la = a - __uint_as_float(h << 16);
    float lb = b - __uint_as_float(h & 0xffff0000u);
    uint32_t l;
    asm("cvt.rn.bf16x2.f32 %0, %1, %2;" : "=r"(l) : "f"(lb), "f"(la));
    hi = h; lo = l;
}

// padded row stride (elements): 4-bank row offset -> conflict-free ldmatrix
#define S64  72     // rows of 64 bf16

// ============================================================================
// Kernel A (d-split): dS^T[dh*64+dl][n] = sum_c V[c][dh*64+dl] * Q[c][n]
// grid = 1024 (cidx*2+dh), 256 threads, 3 CTAs/SM
// ============================================================================
#define KA_SMEM ((size_t)(4*128*S64)*2)   // 73,728 B

__global__ __launch_bounds__(256, 3) void kA(const float* __restrict__ Q,
                                             const float* __restrict__ V) {
    extern __shared__ __nv_bfloat16 sm[];
    __nv_bfloat16* Vh = sm;                  // [128][S64]
    __nv_bfloat16* Vl = Vh + 128 * S64;
    __nv_bfloat16* Qh = Vl + 128 * S64;      // [128][S64]
    __nv_bfloat16* Ql = Qh + 128 * S64;

    const int tid = threadIdx.x, w = tid >> 5, L = tid & 31;
    const int cidx = blockIdx.x >> 1, dh = blockIdx.x & 1;
    const int k = cidx & 15, bh = cidx >> 4;
    const int b = bh >> 3, h = bh & 7;

    const float* Qb = Q + ((size_t)(b * T_ + k * C_) * NH_ + h) * N_;
    const float* Vb = V + (size_t)(b * T_ + k * C_) * D_ + dh * 64;

#pragma unroll
    for (int it = 0; it < 8; it++) {
        int idx = tid + it * 256;                 // 2048 float4
        int n4 = idx & 15, c = idx >> 4;
        float4 q = *(const float4*)(Qb + (size_t)c * (NH_ * N_) + n4 * 4);
        uint32_t h0, l0, h1, l1;
        split2(q.x, q.y, h0, l0);
        split2(q.z, q.w, h1, l1);
        *(uint2*)(Qh + c * S64 + n4 * 4) = make_uint2(h0, h1);
        *(uint2*)(Ql + c * S64 + n4 * 4) = make_uint2(l0, l1);
    }
#pragma unroll
    for (int it = 0; it < 8; it++) {
        int idx = tid + it * 256;                 // 2048 float4
        int d4 = idx & 15, c = idx >> 4;
        float4 v = *(const float4*)(Vb + (size_t)c * D_ + d4 * 4);
        uint32_t h0, l0, h1, l1;
        split2(v.x, v.y, h0, l0);
        split2(v.z, v.w, h1, l1);
        *(uint2*)(Vh + c * S64 + d4 * 4) = make_uint2(h0, h1);
        *(uint2*)(Vl + c * S64 + d4 * 4) = make_uint2(l0, l1);
    }
    __syncthreads();

    const int wd = w & 3, nh = w >> 2;
    const uint32_t aA = smem_u32(
        Vh + ((L & 7) + ((L >> 4) << 3)) * S64 + 16 * wd + (((L >> 3) & 1) << 3));
    const uint32_t VPL = 128 * S64 * 2;          // hi->lo plane (bytes)
    const uint32_t aB = smem_u32((L < 16 ? Qh : Ql) + (L & 15) * S64) + nh * 64;

    float acc[4][4];
#pragma unroll
    for (int j = 0; j < 4; j++)
#pragma unroll
        for (int q = 0; q < 4; q++) acc[j][q] = 0.f;

#pragma unroll
    for (int kk = 0; kk < 8; kk++) {
        uint32_t ah[4], al[4];
        ldmx4t(ah, aA + kk * (16 * S64 * 2));
        ldmx4t(al, aA + VPL + kk * (16 * S64 * 2));
#pragma unroll
        for (int j = 0; j < 4; j++) {
            uint32_t br[4];   // {bh0, bh1, bl0, bl1}
            ldmx4t(br, aB + kk * (16 * S64 * 2) + j * 16);
            mma(acc[j], ah, br);
            mma(acc[j], ah, br + 2);
            mma(acc[j], al, br);
        }
    }

    const int r0 = dh * 64 + 16 * wd + (L >> 2);
    const int cc = nh * 32 + (L & 3) * 2;
    float* op = g_dS + (size_t)cidx * 8192;
#pragma unroll
    for (int j = 0; j < 4; j++) {
        *(float2*)(op + (size_t)r0 * 64 + 8 * j + cc)       = make_float2(acc[j][0], acc[j][1]);
        *(float2*)(op + (size_t)(r0 + 8) * 64 + 8 * j + cc) = make_float2(acc[j][2], acc[j][3]);
    }
}

// ============================================================================
// Kernel B (4-wide): exclusive prefix over the 16 chunks -> bf16 hi/lo planes
// + fp32 new_state.  65536 threads, each owns 4 consecutive n of one (bh,d).
// ============================================================================
__global__ void kB(const float* __restrict__ state, float* __restrict__ out_state) {
    int gid = blockIdx.x * 256 + threadIdx.x;       // < 65536
    int bh = gid >> 11;                             // 32 bh groups
    int e4 = (gid & 2047) * 4;                      // dn base (d = e4>>6, n0 = e4&63)
    int d = e4 >> 6, n0 = e4 & 63;
    const size_t base = (size_t)bh * NC_ * 8192 + e4;
    const size_t stb = ((size_t)bh * 64 + n0) * 128 + d;   // state[n][d], n stride 128

    float4 run;
    run.x = state[stb];
    run.y = state[stb + 128];
    run.z = state[stb + 256];
    run.w = state[stb + 384];
#pragma unroll
    for (int k = 0; k < NC_; k++) {
        float4 v = *(const float4*)(g_dS + base + (size_t)k * 8192);
        uint32_t h01, l01, h23, l23;
        split2(run.x, run.y, h01, l01);
        split2(run.z, run.w, h23, l23);
        *(uint2*)(g_sph + base + (size_t)k * 8192) = make_uint2(h01, h23);
        *(uint2*)(g_spl + base + (size_t)k * 8192) = make_uint2(l01, l23);
        run.x += v.x; run.y += v.y; run.z += v.z; run.w += v.w;
    }
    if (out_state) {
        out_state[stb]       = run.x;
        out_state[stb + 128] = run.y;
        out_state[stb + 256] = run.z;
        out_state[stb + 384] = run.w;
    }
}

// ============================================================================
// Kernel C (d-split + triangular skip + SMSP balance):
//   rb = w<4 ? w : 11-w  (row-block permutation -> equal work per SMSP)
//   scores = tril(Q Q^T, -1): only j-tiles with u-range below the diagonal
//   out[:, dh] = Q @ Spref[:, dh] + scores @ V[:, dh]
// grid = 1024 (cidx*2+dh), 256 threads, 2 CTAs/SM
// ============================================================================
#define KC_SMEM ((size_t)(2*128*S64 + 2*64*S64 + 2*128*S64)*2)   // 92,160 B

__global__ __launch_bounds__(256, 2) void kC(const float* __restrict__ Q,
                                             const float* __restrict__ V,
                                             float* __restrict__ out) {
    extern __shared__ __nv_bfloat16 sm[];
    __nv_bfloat16* Qh = sm;                 // [128][S64]  Q[t][n]
    __nv_bfloat16* Ql = Qh + 128 * S64;
    __nv_bfloat16* Sh = Ql + 128 * S64;     // [64][S64]   Spref^T[d-local][n]
    __nv_bfloat16* Sl = Sh + 64 * S64;
    __nv_bfloat16* Vh = Sl + 64 * S64;      // [128][S64]  V[u][d-local]
    __nv_bfloat16* Vl = Vh + 128 * S64;

    const int tid = threadIdx.x, w = tid >> 5, L = tid & 31;
    const int cidx = blockIdx.x >> 1, dh = blockIdx.x & 1;
    const int k = cidx & 15, bh = cidx >> 4;
    const int b = bh >> 3, h = bh & 7;

    const float* Qb = Q + ((size_t)(b * T_ + k * C_) * NH_ + h) * N_;
    const float* Vb = V + (size_t)(b * T_ + k * C_) * D_ + dh * 64;

    // Q natural [t][n]
#pragma unroll
    for (int it = 0; it < 8; it++) {
        int idx = tid + it * 256;                 // 2048 float4
        int n4 = idx & 15, t = idx >> 4;
        float4 q = *(const float4*)(Qb + (size_t)t * (NH_ * N_) + n4 * 4);
        uint32_t h0, l0, h1, l1;
        split2(q.x, q.y, h0, l0);
        split2(q.z, q.w, h1, l1);
        *(uint2*)(Qh + t * S64 + n4 * 4) = make_uint2(h0, h1);
        *(uint2*)(Ql + t * S64 + n4 * 4) = make_uint2(l0, l1);
    }
    // Spref planes: straight 16B copies of [d][n] bf16 (rows dh*64 .. dh*64+63)
#pragma unroll
    for (int it = 0; it < 2; it++) {
        int idx = tid + it * 256;                 // 512 uint4 per plane
        int ch = idx & 7, dl = idx >> 3;
        size_t sbase = (size_t)cidx * 8192 + (size_t)(dh * 64 + dl) * 64 + ch * 8;
        *(uint4*)(Sh + dl * S64 + ch * 8) = *(const uint4*)(g_sph + sbase);
        *(uint4*)(Sl + dl * S64 + ch * 8) = *(const uint4*)(g_spl + sbase);
    }
    // V natural [u][d-local]
#pragma unroll
    for (int it = 0; it < 8; it++) {
        int idx = tid + it * 256;                 // 2048 float4
        int d4 = idx & 15, u = idx >> 4;
        float4 v = *(const float4*)(Vb + (size_t)u * D_ + d4 * 4);
        uint32_t h0, l0, h1, l1;
        split2(v.x, v.y, h0, l0);
        split2(v.z, v.w, h1, l1);
        *(uint2*)(Vh + u * S64 + d4 * 4) = make_uint2(h0, h1);
        *(uint2*)(Vl + u * S64 + d4 * 4) = make_uint2(l0, l1);
    }
    __syncthreads();

    // SMSP-balanced row-block permutation: pairs (0,7),(1,6),(2,5),(3,4)
    const int rb = (w < 4) ? w : 11 - w;
    const int Lm = L & 15;
    // A (Q rows 16rb..16rb+15) non-trans x4 (per plane)
    const uint32_t aQA = smem_u32(Qh + (16 * rb + Lm) * S64 + ((L >> 4) << 3));
    const uint32_t QOFF = 128 * S64 * 2;     // hi -> lo plane (bytes)
    const uint32_t aQB = smem_u32((L < 16 ? Qh : Ql) + (L & 7) * S64 + (((L >> 3) & 1) << 3));
    const uint32_t aSB = smem_u32((L < 16 ? Sh : Sl) + (L & 7) * S64 + (((L >> 3) & 1) << 3));
    const uint32_t aVB = smem_u32((L < 16 ? Vh : Vl) + (L & 15) * S64);

    const int r0 = 16 * rb + (L >> 2);
    const int jmax = 2 * rb + 2;             // j-tiles with any u below diagonal

    // ---- Phase 1: scores = tril(Q Q^T, -1), skip fully-masked j-tiles ----
    uint32_t PAh[8][4], PAl[8][4];
#pragma unroll
    for (int jb = 0; jb < 2; jb++) {
        const int jlo = jb * 8;
        const int jcnt = min(jmax - jlo, 8);
        if (jcnt <= 0) break;
        float sc[8][4];
#pragma unroll
        for (int j = 0; j < 8; j++)
#pragma unroll
            for (int q = 0; q < 4; q++) sc[j][q] = 0.f;

#pragma unroll
        for (int kk = 0; kk < 4; kk++) {
            uint32_t ah[4], al[4];
            ldmx4(ah, aQA + kk * 32);
            ldmx4(al, aQA + QOFF + kk * 32);
            for (int j = 0; j < jcnt; j++) {
                uint32_t br[4];
                ldmx4(br, aQB + (jlo + j) * (8 * S64 * 2) + kk * 32);
                mma(sc[j], ah, br);
                mma(sc[j], ah, br + 2);
                mma(sc[j], al, br);
            }
        }
        // mask (strict tril) + convert to phase-3 A-fragments
        for (int j = 0; j < jcnt; j++) {
            int jj = jlo + j;
            int u0 = 8 * jj + (L & 3) * 2;
            float x0 = (u0     < r0)     ? sc[j][0] : 0.f;
            float x1 = (u0 + 1 < r0)     ? sc[j][1] : 0.f;
            float x2 = (u0     < r0 + 8) ? sc[j][2] : 0.f;
            float x3 = (u0 + 1 < r0 + 8) ? sc[j][3] : 0.f;
            uint32_t h01, l01, h23, l23;
            split2(x0, x1, h01, l01);
            split2(x2, x3, h23, l23);
            PAh[jj >> 1][(jj & 1) * 2 + 0] = h01;
            PAh[jj >> 1][(jj & 1) * 2 + 1] = h23;
            PAl[jj >> 1][(jj & 1) * 2 + 0] = l01;
            PAl[jj >> 1][(jj & 1) * 2 + 1] = l23;
        }
    }

    // ---- Phase 2: out = Q @ Spref_half (K = 64, j = 8 d-tiles) ----
    float o[8][4];
#pragma unroll
    for (int j = 0; j < 8; j++)
#pragma unroll
        for (int q = 0; q < 4; q++) o[j][q] = 0.f;

#pragma unroll
    for (int kk = 0; kk < 4; kk++) {
        uint32_t ah[4], al[4];
        ldmx4(ah, aQA + kk * 32);
        ldmx4(al, aQA + QOFF + kk * 32);
#pragma unroll
        for (int j = 0; j < 8; j++) {
            uint32_t br[4];
            ldmx4(br, aSB + j * (8 * S64 * 2) + kk * 32);
            mma(o[j], ah, br);
            mma(o[j], ah, br + 2);
            mma(o[j], al, br);
        }
    }

    // ---- Phase 3: out += scores @ V_half (only u-blocks <= diagonal) ----
    for (int kk = 0; kk <= rb; kk++) {
#pragma unroll
        for (int j = 0; j < 8; j++) {
            uint32_t br[4];
            ldmx4t(br, aVB + kk * (16 * S64 * 2) + j * 16);
            mma(o[j], PAh[kk], br);
            mma(o[j], PAh[kk], br + 2);
            mma(o[j], PAl[kk], br);
        }
    }

    // ---- store out[t][dh*64 + d-local] ----
    const int tg = b * T_ + k * C_;
#pragma unroll
    for (int j = 0; j < 8; j++) {
        int d0 = dh * 64 + 8 * j + (L & 3) * 2;
        *(float2*)(out + ((size_t)(tg + r0) * NH_ + h) * D_ + d0) =
            make_float2(o[j][0], o[j][1]);
        *(float2*)(out + ((size_t)(tg + r0 + 8) * NH_ + h) * D_ + d0) =
            make_float2(o[j][2], o[j][3]);
    }
}

// ---------------------------------------------------------------------------
extern "C" void kernel_launch(void* const* d_in, const int* in_sizes, int n_in,
                              void* d_out, int out_size) {
    const float* Q     = (const float*)d_in[0];
    const float* V     = (const float*)d_in[1];
    const float* state = (const float*)d_in[2];
    float* out = (float*)d_out;

    cudaFuncSetAttribute(kA, cudaFuncAttributeMaxDynamicSharedMemorySize, (int)KA_SMEM);
    cudaFuncSetAttribute(kC, cudaFuncAttributeMaxDynamicSharedMemorySize, (int)KC_SMEM);

    bool write_state = (out_size >= (OUT_ELEMS + ST_ELEMS));
    float* out_state = write_state ? (out + OUT_ELEMS) : nullptr;

    kA<<<1024, 256, KA_SMEM>>>(Q, V);
    kB<<<256, 256>>>(state, out_state);
    kC<<<1024, 256, KC_SMEM>>>(Q, V, out);
}

// round 10
// speedup vs baseline: 1.5128x; 1.5128x over previous
#include <cuda_runtime.h>
#include <cuda_bf16.h>
#include <cstdint>

// Problem constants (fixed by the dataset)
#define B_  4
#define T_  2048
#define NH_ 8
#define N_  64
#define D_  128
#define C_  128          // chunk length
#define NC_ 16           // T_/C_
#define OUT_ELEMS (B_*T_*NH_*D_)   // 8,388,608
#define ST_ELEMS  (B_*NH_*N_*D_)   // 262,144

// Scratch:
//  g_dS        : per-chunk delta-state, layout [bh*16+k][d][n] fp32
//  g_sph/g_spl : prefix state (state + sum_{j<k} dS_j), bf16 hi/lo planes, [blk][d][n]
__device__ float         g_dS [(size_t)512*8192];
__device__ __nv_bfloat16 g_sph[(size_t)512*8192];
__device__ __nv_bfloat16 g_spl[(size_t)512*8192];

// ---------------------------------------------------------------------------
// helpers
// ---------------------------------------------------------------------------
__device__ __forceinline__ uint32_t smem_u32(const void* p) {
    uint32_t a;
    asm("{ .reg .u64 t; cvta.to.shared.u64 t, %1; cvt.u32.u64 %0, t; }"
        : "=r"(a) : "l"(p));
    return a;
}
__device__ __forceinline__ void ldmx4(uint32_t* r, uint32_t a) {
    asm volatile("ldmatrix.sync.aligned.m8n8.x4.shared.b16 {%0,%1,%2,%3}, [%4];"
                 : "=r"(r[0]), "=r"(r[1]), "=r"(r[2]), "=r"(r[3]) : "r"(a));
}
__device__ __forceinline__ void ldmx4t(uint32_t* r, uint32_t a) {
    asm volatile("ldmatrix.sync.aligned.m8n8.x4.trans.shared.b16 {%0,%1,%2,%3}, [%4];"
                 : "=r"(r[0]), "=r"(r[1]), "=r"(r[2]), "=r"(r[3]) : "r"(a));
}
// D += A * B, m16n8k16, row.col, bf16 in / fp32 accum
__device__ __forceinline__ void mma(float* d, const uint32_t* a, const uint32_t* b) {
    asm volatile("mma.sync.aligned.m16n8k16.row.col.f32.bf16.bf16.f32 "
                 "{%0,%1,%2,%3}, {%4,%5,%6,%7}, {%8,%9}, {%0,%1,%2,%3};"
                 : "+f"(d[0]), "+f"(d[1]), "+f"(d[2]), "+f"(d[3])
                 : "r"(a[0]), "r"(a[1]), "r"(a[2]), "r"(a[3]),
                   "r"(b[0]), "r"(b[1]));
}
// fp32 pair -> packed bf16x2 hi plane + residual lo plane (a in low half).
__device__ __forceinline__ void split2(float a, float b, uint32_t& hi, uint32_t& lo) {
    uint32_t h;
    asm("cvt.rn.bf16x2.f32 %0, %1, %2;" : "=r"(h) : "f"(b), "f"(a));
    float la = a - __uint_as_float(h << 16);
    float lb = b - __uint_as_float(h & 0xffff0000u);
    uint32_t l;
    asm("cvt.rn.bf16x2.f32 %0, %1, %2;" : "=r"(l) : "f"(lb), "f"(la));
    hi = h; lo = l;
}

// padded row stride (elements): 4-bank row offset -> conflict-free ldmatrix
#define S64  72     // rows of 64 bf16

// ============================================================================
// Kernel A (d-split): dS^T[dh*64+dl][n] = sum_c V[c][dh*64+dl] * Q[c][n]
// grid = 1024 (cidx*2+dh), 256 threads, 3 CTAs/SM
// ============================================================================
#define KA_SMEM ((size_t)(4*128*S64)*2)   // 73,728 B

__global__ __launch_bounds__(256, 3) void kA(const float* __restrict__ Q,
                                             const float* __restrict__ V) {
    extern __shared__ __nv_bfloat16 sm[];
    __nv_bfloat16* Vh = sm;                  // [128][S64]
    __nv_bfloat16* Vl = Vh + 128 * S64;
    __nv_bfloat16* Qh = Vl + 128 * S64;      // [128][S64]
    __nv_bfloat16* Ql = Qh + 128 * S64;

    const int tid = threadIdx.x, w = tid >> 5, L = tid & 31;
    const int cidx = blockIdx.x >> 1, dh = blockIdx.x & 1;
    const int k = cidx & 15, bh = cidx >> 4;
    const int b = bh >> 3, h = bh & 7;

    const float* Qb = Q + ((size_t)(b * T_ + k * C_) * NH_ + h) * N_;
    const float* Vb = V + (size_t)(b * T_ + k * C_) * D_ + dh * 64;

#pragma unroll
    for (int it = 0; it < 8; it++) {
        int idx = tid + it * 256;                 // 2048 float4
        int n4 = idx & 15, c = idx >> 4;
        float4 q = *(const float4*)(Qb + (size_t)c * (NH_ * N_) + n4 * 4);
        uint32_t h0, l0, h1, l1;
        split2(q.x, q.y, h0, l0);
        split2(q.z, q.w, h1, l1);
        *(uint2*)(Qh + c * S64 + n4 * 4) = make_uint2(h0, h1);
        *(uint2*)(Ql + c * S64 + n4 * 4) = make_uint2(l0, l1);
    }
#pragma unroll
    for (int it = 0; it < 8; it++) {
        int idx = tid + it * 256;                 // 2048 float4
        int d4 = idx & 15, c = idx >> 4;
        float4 v = *(const float4*)(Vb + (size_t)c * D_ + d4 * 4);
        uint32_t h0, l0, h1, l1;
        split2(v.x, v.y, h0, l0);
        split2(v.z, v.w, h1, l1);
        *(uint2*)(Vh + c * S64 + d4 * 4) = make_uint2(h0, h1);
        *(uint2*)(Vl + c * S64 + d4 * 4) = make_uint2(l0, l1);
    }
    __syncthreads();

    const int wd = w & 3, nh = w >> 2;
    const uint32_t aA = smem_u32(
        Vh + ((L & 7) + ((L >> 4) << 3)) * S64 + 16 * wd + (((L >> 3) & 1) << 3));
    const uint32_t VPL = 128 * S64 * 2;          // hi->lo plane (bytes)
    const uint32_t aB = smem_u32((L < 16 ? Qh : Ql) + (L & 15) * S64) + nh * 64;

    float acc[4][4];
#pragma unroll
    for (int j = 0; j < 4; j++)
#pragma unroll
        for (int q = 0; q < 4; q++) acc[j][q] = 0.f;

#pragma unroll
    for (int kk = 0; kk < 8; kk++) {
        uint32_t ah[4], al[4];
        ldmx4t(ah, aA + kk * (16 * S64 * 2));
        ldmx4t(al, aA + VPL + kk * (16 * S64 * 2));
#pragma unroll
        for (int j = 0; j < 4; j++) {
            uint32_t br[4];   // {bh0, bh1, bl0, bl1}
            ldmx4t(br, aB + kk * (16 * S64 * 2) + j * 16);
            mma(acc[j], ah, br);
            mma(acc[j], ah, br + 2);
            mma(acc[j], al, br);
        }
    }

    const int r0 = dh * 64 + 16 * wd + (L >> 2);
    const int cc = nh * 32 + (L & 3) * 2;
    float* op = g_dS + (size_t)cidx * 8192;
#pragma unroll
    for (int j = 0; j < 4; j++) {
        *(float2*)(op + (size_t)r0 * 64 + 8 * j + cc)       = make_float2(acc[j][0], acc[j][1]);
        *(float2*)(op + (size_t)(r0 + 8) * 64 + 8 * j + cc) = make_float2(acc[j][2], acc[j][3]);
    }
}

// ============================================================================
// Kernel B (4-wide): exclusive prefix over the 16 chunks -> bf16 hi/lo planes
// + fp32 new_state.  65536 threads, each owns 4 consecutive n of one (bh,d).
// ============================================================================
__global__ void kB(const float* __restrict__ state, float* __restrict__ out_state) {
    int gid = blockIdx.x * 256 + threadIdx.x;       // < 65536
    int bh = gid >> 11;                             // 32 bh groups
    int e4 = (gid & 2047) * 4;                      // dn base (d = e4>>6, n0 = e4&63)
    int d = e4 >> 6, n0 = e4 & 63;
    const size_t base = (size_t)bh * NC_ * 8192 + e4;
    const size_t stb = ((size_t)bh * 64 + n0) * 128 + d;   // state[n][d], n stride 128

    float4 run;
    run.x = state[stb];
    run.y = state[stb + 128];
    run.z = state[stb + 256];
    run.w = state[stb + 384];
#pragma unroll
    for (int k = 0; k < NC_; k++) {
        float4 v = *(const float4*)(g_dS + base + (size_t)k * 8192);
        uint32_t h01, l01, h23, l23;
        split2(run.x, run.y, h01, l01);
        split2(run.z, run.w, h23, l23);
        *(uint2*)(g_sph + base + (size_t)k * 8192) = make_uint2(h01, h23);
        *(uint2*)(g_spl + base + (size_t)k * 8192) = make_uint2(l01, l23);
        run.x += v.x; run.y += v.y; run.z += v.z; run.w += v.w;
    }
    if (out_state) {
        out_state[stb]       = run.x;
        out_state[stb + 128] = run.y;
        out_state[stb + 256] = run.z;
        out_state[stb + 384] = run.w;
    }
}

// ============================================================================
// Kernel C (d-split + triangular skip via UNROLLED warp-uniform predication):
//   rb = w<4 ? w : 11-w  (row-block permutation -> equal work per SMSP)
//   Phase 1: only j-tiles with u-range at/below the diagonal (jj < 2rb+2)
//   Phase 3: only u-blocks kk <= rb
//   All loops fully unrolled; all register indices compile-time constants.
// grid = 1024 (cidx*2+dh), 256 threads, 2 CTAs/SM
// ============================================================================
#define KC_SMEM ((size_t)(2*128*S64 + 2*64*S64 + 2*128*S64)*2)   // 92,160 B

__global__ __launch_bounds__(256, 2) void kC(const float* __restrict__ Q,
                                             const float* __restrict__ V,
                                             float* __restrict__ out) {
    extern __shared__ __nv_bfloat16 sm[];
    __nv_bfloat16* Qh = sm;                 // [128][S64]  Q[t][n]
    __nv_bfloat16* Ql = Qh + 128 * S64;
    __nv_bfloat16* Sh = Ql + 128 * S64;     // [64][S64]   Spref^T[d-local][n]
    __nv_bfloat16* Sl = Sh + 64 * S64;
    __nv_bfloat16* Vh = Sl + 64 * S64;      // [128][S64]  V[u][d-local]
    __nv_bfloat16* Vl = Vh + 128 * S64;

    const int tid = threadIdx.x, w = tid >> 5, L = tid & 31;
    const int cidx = blockIdx.x >> 1, dh = blockIdx.x & 1;
    const int k = cidx & 15, bh = cidx >> 4;
    const int b = bh >> 3, h = bh & 7;

    const float* Qb = Q + ((size_t)(b * T_ + k * C_) * NH_ + h) * N_;
    const float* Vb = V + (size_t)(b * T_ + k * C_) * D_ + dh * 64;

    // Q natural [t][n]
#pragma unroll
    for (int it = 0; it < 8; it++) {
        int idx = tid + it * 256;                 // 2048 float4
        int n4 = idx & 15, t = idx >> 4;
        float4 q = *(const float4*)(Qb + (size_t)t * (NH_ * N_) + n4 * 4);
        uint32_t h0, l0, h1, l1;
        split2(q.x, q.y, h0, l0);
        split2(q.z, q.w, h1, l1);
        *(uint2*)(Qh + t * S64 + n4 * 4) = make_uint2(h0, h1);
        *(uint2*)(Ql + t * S64 + n4 * 4) = make_uint2(l0, l1);
    }
    // Spref planes: straight 16B copies of [d][n] bf16 (rows dh*64 .. dh*64+63)
#pragma unroll
    for (int it = 0; it < 2; it++) {
        int idx = tid + it * 256;                 // 512 uint4 per plane
        int ch = idx & 7, dl = idx >> 3;
        size_t sbase = (size_t)cidx * 8192 + (size_t)(dh * 64 + dl) * 64 + ch * 8;
        *(uint4*)(Sh + dl * S64 + ch * 8) = *(const uint4*)(g_sph + sbase);
        *(uint4*)(Sl + dl * S64 + ch * 8) = *(const uint4*)(g_spl + sbase);
    }
    // V natural [u][d-local]
#pragma unroll
    for (int it = 0; it < 8; it++) {
        int idx = tid + it * 256;                 // 2048 float4
        int d4 = idx & 15, u = idx >> 4;
        float4 v = *(const float4*)(Vb + (size_t)u * D_ + d4 * 4);
        uint32_t h0, l0, h1, l1;
        split2(v.x, v.y, h0, l0);
        split2(v.z, v.w, h1, l1);
        *(uint2*)(Vh + u * S64 + d4 * 4) = make_uint2(h0, h1);
        *(uint2*)(Vl + u * S64 + d4 * 4) = make_uint2(l0, l1);
    }
    __syncthreads();

    // SMSP-balanced row-block permutation: pairs (0,7),(1,6),(2,5),(3,4)
    const int rb = (w < 4) ? w : 11 - w;
    const int Lm = L & 15;
    // A (Q rows 16rb..16rb+15) non-trans x4 (per plane)
    const uint32_t aQA = smem_u32(Qh + (16 * rb + Lm) * S64 + ((L >> 4) << 3));
    const uint32_t QOFF = 128 * S64 * 2;     // hi -> lo plane (bytes)
    const uint32_t aQB = smem_u32((L < 16 ? Qh : Ql) + (L & 7) * S64 + (((L >> 3) & 1) << 3));
    const uint32_t aSB = smem_u32((L < 16 ? Sh : Sl) + (L & 7) * S64 + (((L >> 3) & 1) << 3));
    const uint32_t aVB = smem_u32((L < 16 ? Vh : Vl) + (L & 15) * S64);

    const int r0 = 16 * rb + (L >> 2);
    const int jmax = 2 * rb + 2;             // j-tiles with any u at/below diagonal

    // ---- Phase 1: scores = tril(Q Q^T, -1), unrolled + uniform predication ----
    uint32_t PAh[8][4], PAl[8][4];
#pragma unroll
    for (int j = 0; j < 8; j++)
#pragma unroll
        for (int q = 0; q < 4; q++) { PAh[j][q] = 0u; PAl[j][q] = 0u; }

#pragma unroll
    for (int jb = 0; jb < 2; jb++) {
        if (jb * 8 < jmax) {                  // warp-uniform
            float sc[8][4];
#pragma unroll
            for (int j = 0; j < 8; j++)
#pragma unroll
                for (int q = 0; q < 4; q++) sc[j][q] = 0.f;

#pragma unroll
            for (int kk = 0; kk < 4; kk++) {
                uint32_t ah[4], al[4];
                ldmx4(ah, aQA + kk * 32);
                ldmx4(al, aQA + QOFF + kk * 32);
#pragma unroll
                for (int j = 0; j < 8; j++) {
                    if (jb * 8 + j < jmax) {  // warp-uniform, compile-time index
                        uint32_t br[4];
                        ldmx4(br, aQB + (jb * 8 + j) * (8 * S64 * 2) + kk * 32);
                        mma(sc[j], ah, br);
                        mma(sc[j], ah, br + 2);
                        mma(sc[j], al, br);
                    }
                }
            }
            // mask (strict tril) + convert to phase-3 A-fragments
#pragma unroll
            for (int j = 0; j < 8; j++) {
                if (jb * 8 + j < jmax) {
                    const int jj = jb * 8 + j;
                    int u0 = 8 * jj + (L & 3) * 2;
                    float x0 = (u0     < r0)     ? sc[j][0] : 0.f;
                    float x1 = (u0 + 1 < r0)     ? sc[j][1] : 0.f;
                    float x2 = (u0     < r0 + 8) ? sc[j][2] : 0.f;
                    float x3 = (u0 + 1 < r0 + 8) ? sc[j][3] : 0.f;
                    uint32_t h01, l01, h23, l23;
                    split2(x0, x1, h01, l01);
                    split2(x2, x3, h23, l23);
                    PAh[jj >> 1][(jj & 1) * 2 + 0] = h01;
                    PAh[jj >> 1][(jj & 1) * 2 + 1] = h23;
                    PAl[jj >> 1][(jj & 1) * 2 + 0] = l01;
                    PAl[jj >> 1][(jj & 1) * 2 + 1] = l23;
                }
            }
        }
    }

    // ---- Phase 2: out = Q @ Spref_half (K = 64, j = 8 d-tiles) ----
    float o[8][4];
#pragma unroll
    for (int j = 0; j < 8; j++)
#pragma unroll
        for (int q = 0; q < 4; q++) o[j][q] = 0.f;

#pragma unroll
    for (int kk = 0; kk < 4; kk++) {
        uint32_t ah[4], al[4];
        ldmx4(ah, aQA + kk * 32);
        ldmx4(al, aQA + QOFF + kk * 32);
#pragma unroll
        for (int j = 0; j < 8; j++) {
            uint32_t br[4];
            ldmx4(br, aSB + j * (8 * S64 * 2) + kk * 32);
            mma(o[j], ah, br);
            mma(o[j], ah, br + 2);
            mma(o[j], al, br);
        }
    }

    // ---- Phase 3: out += scores @ V_half (unrolled, kk <= rb predicated) ----
#pragma unroll
    for (int kk = 0; kk < 8; kk++) {
        if (kk <= rb) {                       // warp-uniform, static PA index
#pragma unroll
            for (int j = 0; j < 8; j++) {
                uint32_t br[4];
                ldmx4t(br, aVB + kk * (16 * S64 * 2) + j * 16);
                mma(o[j], PAh[kk], br);
                mma(o[j], PAh[kk], br + 2);
                mma(o[j], PAl[kk], br);
            }
        }
    }

    // ---- store out[t][dh*64 + d-local] ----
    const int tg = b * T_ + k * C_;
#pragma unroll
    for (int j = 0; j < 8; j++) {
        int d0 = dh * 64 + 8 * j + (L & 3) * 2;
        *(float2*)(out + ((size_t)(tg + r0) * NH_ + h) * D_ + d0) =
            make_float2(o[j][0], o[j][1]);
        *(float2*)(out + ((size_t)(tg + r0 + 8) * NH_ + h) * D_ + d0) =
            make_float2(o[j][2], o[j][3]);
    }
}

// ---------------------------------------------------------------------------
extern "C" void kernel_launch(void* const* d_in, const int* in_sizes, int n_in,
                              void* d_out, int out_size) {
    const float* Q     = (const float*)d_in[0];
    const float* V     = (const float*)d_in[1];
    const float* state = (const float*)d_in[2];
    float* out = (float*)d_out;

    cudaFuncSetAttribute(kA, cudaFuncAttributeMaxDynamicSharedMemorySize, (int)KA_SMEM);
    cudaFuncSetAttribute(kC, cudaFuncAttributeMaxDynamicSharedMemorySize, (int)KC_SMEM);

    bool write_state = (out_size >= (OUT_ELEMS + ST_ELEMS));
    float* out_state = write_state ? (out + OUT_ELEMS) : nullptr;

    kA<<<1024, 256, KA_SMEM>>>(Q, V);
    kB<<<256, 256>>>(state, out_state);
    kC<<<1024, 256, KC_SMEM>>>(Q, V, out);
}

// round 11
// speedup vs baseline: 2.2566x; 1.4916x over previous
#include <cuda_runtime.h>
#include <cuda_fp16.h>
#include <cstdint>

// Problem constants (fixed by the dataset)
#define B_  4
#define T_  2048
#define NH_ 8
#define N_  64
#define D_  128
#define C_  128          // chunk length
#define NC_ 16           // T_/C_
#define OUT_ELEMS (B_*T_*NH_*D_)   // 8,388,608
#define ST_ELEMS  (B_*NH_*N_*D_)   // 262,144

// Scratch:
//  g_dS  : per-chunk delta-state, layout [bh*16+k][d][n] fp32
//  g_spf : prefix state (state + sum_{j<k} dS_j), fp16, [blk][d][n]
__device__ float  g_dS [(size_t)512*8192];
__device__ __half g_spf[(size_t)512*8192];

// ---------------------------------------------------------------------------
// helpers
// ---------------------------------------------------------------------------
__device__ __forceinline__ uint32_t smem_u32(const void* p) {
    uint32_t a;
    asm("{ .reg .u64 t; cvta.to.shared.u64 t, %1; cvt.u32.u64 %0, t; }"
        : "=r"(a) : "l"(p));
    return a;
}
__device__ __forceinline__ void ldmx4(uint32_t* r, uint32_t a) {
    asm volatile("ldmatrix.sync.aligned.m8n8.x4.shared.b16 {%0,%1,%2,%3}, [%4];"
                 : "=r"(r[0]), "=r"(r[1]), "=r"(r[2]), "=r"(r[3]) : "r"(a));
}
__device__ __forceinline__ void ldmx4t(uint32_t* r, uint32_t a) {
    asm volatile("ldmatrix.sync.aligned.m8n8.x4.trans.shared.b16 {%0,%1,%2,%3}, [%4];"
                 : "=r"(r[0]), "=r"(r[1]), "=r"(r[2]), "=r"(r[3]) : "r"(a));
}
// D += A * B, m16n8k16, row.col, fp16 in / fp32 accum
__device__ __forceinline__ void mma(float* d, const uint32_t* a, const uint32_t* b) {
    asm volatile("mma.sync.aligned.m16n8k16.row.col.f32.f16.f16.f32 "
                 "{%0,%1,%2,%3}, {%4,%5,%6,%7}, {%8,%9}, {%0,%1,%2,%3};"
                 : "+f"(d[0]), "+f"(d[1]), "+f"(d[2]), "+f"(d[3])
                 : "r"(a[0]), "r"(a[1]), "r"(a[2]), "r"(a[3]),
                   "r"(b[0]), "r"(b[1]));
}
// pack two fp32 -> fp16x2 (a in low half)
__device__ __forceinline__ uint32_t pk2(float a, float b) {
    uint32_t r;
    asm("cvt.rn.f16x2.f32 %0, %1, %2;" : "=r"(r) : "f"(b), "f"(a));
    return r;
}

// padded row strides (fp16 elements): rows step 4 banks -> conflict-free ldmatrix
#define S64  72     // rows of 64 fp16
#define S128 136    // rows of 128 fp16

// ============================================================================
// Kernel A (full d): dS^T[d][n] = sum_c V[c][d] * Q[c][n]
//   smem: V natural [c=128][d=128], Q natural [c=128][n=64] (fp16)
//   A = V^T (ldmatrix.trans), B = Q^T (ldmatrix.trans)
// grid = 512 (bh*16+k), 256 threads, 3 CTAs/SM; warp w owns d rows 16w..16w+15
// ============================================================================
#define KA_SMEM ((size_t)(128*S128 + 128*S64)*2)   // 53,248 B

__global__ __launch_bounds__(256, 3) void kA(const float* __restrict__ Q,
                                             const float* __restrict__ V) {
    extern __shared__ __half sm[];
    __half* Vf = sm;                 // [128][S128]
    __half* Qf = Vf + 128 * S128;    // [128][S64]

    const int tid = threadIdx.x, w = tid >> 5, L = tid & 31;
    const int cidx = blockIdx.x;
    const int k = cidx & 15, bh = cidx >> 4;
    const int b = bh >> 3, h = bh & 7;

    const float* Qb = Q + ((size_t)(b * T_ + k * C_) * NH_ + h) * N_;
    const float* Vb = V + (size_t)(b * T_ + k * C_) * D_;

    // Q natural [c][n]
#pragma unroll
    for (int it = 0; it < 8; it++) {
        int idx = tid + it * 256;                 // 2048 float4
        int n4 = idx & 15, c = idx >> 4;
        float4 q = *(const float4*)(Qb + (size_t)c * (NH_ * N_) + n4 * 4);
        *(uint2*)(Qf + c * S64 + n4 * 4) = make_uint2(pk2(q.x, q.y), pk2(q.z, q.w));
    }
    // V natural [c][d]
#pragma unroll
    for (int it = 0; it < 16; it++) {
        int idx = tid + it * 256;                 // 4096 float4
        int d4 = idx & 31, c = idx >> 5;
        float4 v = *(const float4*)(Vb + (size_t)c * D_ + d4 * 4);
        *(uint2*)(Vf + c * S128 + d4 * 4) = make_uint2(pk2(v.x, v.y), pk2(v.z, v.w));
    }
    __syncthreads();

    // A (V^T, m = d rows 16w..16w+15) trans x4
    const uint32_t aA = smem_u32(
        Vf + ((L & 7) + ((L >> 4) << 3)) * S128 + 16 * w + (((L >> 3) & 1) << 3));
    // B (Q^T) trans x4: 2 n-tiles (16 cols) per ldmatrix
    const uint32_t aB = smem_u32(Qf + (L & 15) * S64 + ((L >> 4) << 3));

    float acc[8][4];
#pragma unroll
    for (int j = 0; j < 8; j++)
#pragma unroll
        for (int q = 0; q < 4; q++) acc[j][q] = 0.f;

#pragma unroll
    for (int kk = 0; kk < 8; kk++) {
        uint32_t a4[4];
        ldmx4t(a4, aA + kk * (16 * S128 * 2));
#pragma unroll
        for (int jp = 0; jp < 4; jp++) {
            uint32_t br[4];   // {b0(j0), b1(j0), b0(j1), b1(j1)}
            ldmx4t(br, aB + kk * (16 * S64 * 2) + jp * 32);
            mma(acc[2 * jp],     a4, br);
            mma(acc[2 * jp + 1], a4, br + 2);
        }
    }

    const int r0 = 16 * w + (L >> 2);
    const int cc = (L & 3) * 2;
    float* op = g_dS + (size_t)cidx * 8192;
#pragma unroll
    for (int j = 0; j < 8; j++) {
        *(float2*)(op + (size_t)r0 * 64 + 8 * j + cc)       = make_float2(acc[j][0], acc[j][1]);
        *(float2*)(op + (size_t)(r0 + 8) * 64 + 8 * j + cc) = make_float2(acc[j][2], acc[j][3]);
    }
}

// ============================================================================
// Kernel B (4-wide): exclusive prefix over the 16 chunks -> fp16 plane + fp32
// new_state.  65536 threads, each owns 4 consecutive n of one (bh,d).
// ============================================================================
__global__ void kB(const float* __restrict__ state, float* __restrict__ out_state) {
    int gid = blockIdx.x * 256 + threadIdx.x;       // < 65536
    int bh = gid >> 11;
    int e4 = (gid & 2047) * 4;
    int d = e4 >> 6, n0 = e4 & 63;
    const size_t base = (size_t)bh * NC_ * 8192 + e4;
    const size_t stb = ((size_t)bh * 64 + n0) * 128 + d;   // state[n][d], n stride 128

    float4 run;
    run.x = state[stb];
    run.y = state[stb + 128];
    run.z = state[stb + 256];
    run.w = state[stb + 384];
#pragma unroll
    for (int k = 0; k < NC_; k++) {
        float4 v = *(const float4*)(g_dS + base + (size_t)k * 8192);
        *(uint2*)(g_spf + base + (size_t)k * 8192) =
            make_uint2(pk2(run.x, run.y), pk2(run.z, run.w));
        run.x += v.x; run.y += v.y; run.z += v.z; run.w += v.w;
    }
    if (out_state) {
        out_state[stb]       = run.x;
        out_state[stb + 128] = run.y;
        out_state[stb + 256] = run.z;
        out_state[stb + 384] = run.w;
    }
}

// ============================================================================
// Kernel C (d-split + triangular skip, fp16 single-pass):
//   rb = w<4 ? w : 11-w  (SMSP-balanced row blocks)
//   Phase 1: scores = tril(Q Q^T, -1), only u-blocks jp <= rb   -> PA frags
//   Phase 2: out  = Q @ Spref_half
//   Phase 3: out += scores @ V_half, only u-blocks kk <= rb
// grid = 1024 (cidx*2+dh), 256 threads, 3 CTAs/SM
// ============================================================================
#define KC_SMEM ((size_t)(128*S64 + 64*S64 + 128*S64)*2)   // 46,080 B

__global__ __launch_bounds__(256, 3) void kC(const float* __restrict__ Q,
                                             const float* __restrict__ V,
                                             float* __restrict__ out) {
    extern __shared__ __half sm[];
    __half* Qf = sm;                 // [128][S64]  Q[t][n]
    __half* Sf = Qf + 128 * S64;     // [64][S64]   Spref^T[d-local][n]
    __half* Vf = Sf + 64 * S64;      // [128][S64]  V[u][d-local]

    const int tid = threadIdx.x, w = tid >> 5, L = tid & 31;
    const int cidx = blockIdx.x >> 1, dh = blockIdx.x & 1;
    const int k = cidx & 15, bh = cidx >> 4;
    const int b = bh >> 3, h = bh & 7;

    const float* Qb = Q + ((size_t)(b * T_ + k * C_) * NH_ + h) * N_;
    const float* Vb = V + (size_t)(b * T_ + k * C_) * D_ + dh * 64;

    // Q natural [t][n]
#pragma unroll
    for (int it = 0; it < 8; it++) {
        int idx = tid + it * 256;                 // 2048 float4
        int n4 = idx & 15, t = idx >> 4;
        float4 q = *(const float4*)(Qb + (size_t)t * (NH_ * N_) + n4 * 4);
        *(uint2*)(Qf + t * S64 + n4 * 4) = make_uint2(pk2(q.x, q.y), pk2(q.z, q.w));
    }
    // Spref plane: straight 16B copies of [d][n] fp16 (rows dh*64 .. dh*64+63)
#pragma unroll
    for (int it = 0; it < 2; it++) {
        int idx = tid + it * 256;                 // 512 uint4
        int ch = idx & 7, dl = idx >> 3;
        size_t sbase = (size_t)cidx * 8192 + (size_t)(dh * 64 + dl) * 64 + ch * 8;
        *(uint4*)(Sf + dl * S64 + ch * 8) = *(const uint4*)(g_spf + sbase);
    }
    // V natural [u][d-local]
#pragma unroll
    for (int it = 0; it < 8; it++) {
        int idx = tid + it * 256;                 // 2048 float4
        int d4 = idx & 15, u = idx >> 4;
        float4 v = *(const float4*)(Vb + (size_t)u * D_ + d4 * 4);
        *(uint2*)(Vf + u * S64 + d4 * 4) = make_uint2(pk2(v.x, v.y), pk2(v.z, v.w));
    }
    __syncthreads();

    // SMSP-balanced row-block permutation: pairs (0,7),(1,6),(2,5),(3,4)
    const int rb = (w < 4) ? w : 11 - w;
    const int Lm = L & 15;
    // A (Q rows 16rb..16rb+15) non-trans x4
    const uint32_t aQA = smem_u32(Qf + (16 * rb + Lm) * S64 + ((L >> 4) << 3));
    // B non-trans x4: 2 j-tiles per ldmatrix (rows (L&7)+((L>>4)<<3), col-half (L>>3)&1)
    const uint32_t aQB = smem_u32(
        Qf + ((L & 7) + ((L >> 4) << 3)) * S64 + (((L >> 3) & 1) << 3));
    const uint32_t aSB = smem_u32(
        Sf + ((L & 7) + ((L >> 4) << 3)) * S64 + (((L >> 3) & 1) << 3));
    // B (V^T) trans x4: 2 d-tiles per ldmatrix
    const uint32_t aVB = smem_u32(Vf + (L & 15) * S64 + ((L >> 4) << 3));

    const int r0 = 16 * rb + (L >> 2);

    // A fragments for all 4 k16 blocks (n = 0..63): reused by phases 1 and 2
    uint32_t Aall[4][4];
#pragma unroll
    for (int kk = 0; kk < 4; kk++) ldmx4(Aall[kk], aQA + kk * 32);

    // ---- Phase 1: scores = tril(Q Q^T, -1); PA[kk] covers u = 16kk..16kk+15 ----
    uint32_t PA[8][4];
#pragma unroll
    for (int j = 0; j < 8; j++)
#pragma unroll
        for (int q = 0; q < 4; q++) PA[j][q] = 0u;

#pragma unroll
    for (int jp = 0; jp < 8; jp++) {
        if (jp <= rb) {                           // warp-uniform
            float sc0[4] = {0.f, 0.f, 0.f, 0.f};
            float sc1[4] = {0.f, 0.f, 0.f, 0.f};
#pragma unroll
            for (int kk = 0; kk < 4; kk++) {
                uint32_t br[4];
                ldmx4(br, aQB + jp * (16 * S64 * 2) + kk * 32);
                mma(sc0, Aall[kk], br);
                mma(sc1, Aall[kk], br + 2);
            }
            // strict tril mask + fp16 A-fragment packing
            int u0 = 16 * jp + (L & 3) * 2;
            float x0 = (u0     < r0)     ? sc0[0] : 0.f;
            float x1 = (u0 + 1 < r0)     ? sc0[1] : 0.f;
            float x2 = (u0     < r0 + 8) ? sc0[2] : 0.f;
            float x3 = (u0 + 1 < r0 + 8) ? sc0[3] : 0.f;
            float y0 = (u0 + 8 < r0)     ? sc1[0] : 0.f;
            float y1 = (u0 + 9 < r0)     ? sc1[1] : 0.f;
            float y2 = (u0 + 8 < r0 + 8) ? sc1[2] : 0.f;
            float y3 = (u0 + 9 < r0 + 8) ? sc1[3] : 0.f;
            PA[jp][0] = pk2(x0, x1);
            PA[jp][1] = pk2(x2, x3);
            PA[jp][2] = pk2(y0, y1);
            PA[jp][3] = pk2(y2, y3);
        }
    }

    // ---- Phase 2: out = Q @ Spref_half (K = 64, 8 d-tiles) ----
    float o[8][4];
#pragma unroll
    for (int j = 0; j < 8; j++)
#pragma unroll
        for (int q = 0; q < 4; q++) o[j][q] = 0.f;

#pragma unroll
    for (int kk = 0; kk < 4; kk++) {
#pragma unroll
        for (int jp = 0; jp < 4; jp++) {
            uint32_t br[4];
            ldmx4(br, aSB + jp * (16 * S64 * 2) + kk * 32);
            mma(o[2 * jp],     Aall[kk], br);
            mma(o[2 * jp + 1], Aall[kk], br + 2);
        }
    }

    // ---- Phase 3: out += scores @ V_half (kk <= rb, unrolled predication) ----
#pragma unroll
    for (int kk = 0; kk < 8; kk++) {
        if (kk <= rb) {                           // warp-uniform, static PA index
#pragma unroll
            for (int jp = 0; jp < 4; jp++) {
                uint32_t br[4];
                ldmx4t(br, aVB + kk * (16 * S64 * 2) + jp * 32);
                mma(o[2 * jp],     PA[kk], br);
                mma(o[2 * jp + 1], PA[kk], br + 2);
            }
        }
    }

    // ---- store out[t][dh*64 + d-local] ----
    const int tg = b * T_ + k * C_;
#pragma unroll
    for (int j = 0; j < 8; j++) {
        int d0 = dh * 64 + 8 * j + (L & 3) * 2;
        *(float2*)(out + ((size_t)(tg + r0) * NH_ + h) * D_ + d0) =
            make_float2(o[j][0], o[j][1]);
        *(float2*)(out + ((size_t)(tg + r0 + 8) * NH_ + h) * D_ + d0) =
            make_float2(o[j][2], o[j][3]);
    }
}

// ---------------------------------------------------------------------------
extern "C" void kernel_launch(void* const* d_in, const int* in_sizes, int n_in,
                              void* d_out, int out_size) {
    const float* Q     = (const float*)d_in[0];
    const float* V     = (const float*)d_in[1];
    const float* state = (const float*)d_in[2];
    float* out = (float*)d_out;

    cudaFuncSetAttribute(kA, cudaFuncAttributeMaxDynamicSharedMemorySize, (int)KA_SMEM);
    cudaFuncSetAttribute(kC, cudaFuncAttributeMaxDynamicSharedMemorySize, (int)KC_SMEM);

    bool write_state = (out_size >= (OUT_ELEMS + ST_ELEMS));
    float* out_state = write_state ? (out + OUT_ELEMS) : nullptr;

    kA<<<512, 256, KA_SMEM>>>(Q, V);
    kB<<<256, 256>>>(state, out_state);
    kC<<<1024, 256, KC_SMEM>>>(Q, V, out);
}

// round 12
// speedup vs baseline: 2.5652x; 1.1368x over previous
#include <cuda_runtime.h>
#include <cuda_fp16.h>
#include <cstdint>

// Problem constants (fixed by the dataset)
#define B_  4
#define T_  2048
#define NH_ 8
#define N_  64
#define D_  128
#define C_  128          // chunk length
#define NC_ 16           // T_/C_
#define OUT_ELEMS (B_*T_*NH_*D_)   // 8,388,608
#define ST_ELEMS  (B_*NH_*N_*D_)   // 262,144

// Scratch:
//  g_dS  : per-chunk delta-state, layout [bh*16+k][d][n] fp32
//  g_spf : prefix state (state + sum_{j<k} dS_j), fp16, [blk][d][n]
__device__ float  g_dS [(size_t)512*8192];
__device__ __half g_spf[(size_t)512*8192];

// ---------------------------------------------------------------------------
// helpers
// ---------------------------------------------------------------------------
__device__ __forceinline__ uint32_t smem_u32(const void* p) {
    uint32_t a;
    asm("{ .reg .u64 t; cvta.to.shared.u64 t, %1; cvt.u32.u64 %0, t; }"
        : "=r"(a) : "l"(p));
    return a;
}
__device__ __forceinline__ void ldmx4(uint32_t* r, uint32_t a) {
    asm volatile("ldmatrix.sync.aligned.m8n8.x4.shared.b16 {%0,%1,%2,%3}, [%4];"
                 : "=r"(r[0]), "=r"(r[1]), "=r"(r[2]), "=r"(r[3]) : "r"(a));
}
__device__ __forceinline__ void ldmx4t(uint32_t* r, uint32_t a) {
    asm volatile("ldmatrix.sync.aligned.m8n8.x4.trans.shared.b16 {%0,%1,%2,%3}, [%4];"
                 : "=r"(r[0]), "=r"(r[1]), "=r"(r[2]), "=r"(r[3]) : "r"(a));
}
// D += A * B, m16n8k16, row.col, fp16 in / fp32 accum
__device__ __forceinline__ void mma(float* d, const uint32_t* a, const uint32_t* b) {
    asm volatile("mma.sync.aligned.m16n8k16.row.col.f32.f16.f16.f32 "
                 "{%0,%1,%2,%3}, {%4,%5,%6,%7}, {%8,%9}, {%0,%1,%2,%3};"
                 : "+f"(d[0]), "+f"(d[1]), "+f"(d[2]), "+f"(d[3])
                 : "r"(a[0]), "r"(a[1]), "r"(a[2]), "r"(a[3]),
                   "r"(b[0]), "r"(b[1]));
}
// pack two fp32 -> fp16x2 (a in low half)
__device__ __forceinline__ uint32_t pk2(float a, float b) {
    uint32_t r;
    asm("cvt.rn.f16x2.f32 %0, %1, %2;" : "=r"(r) : "f"(b), "f"(a));
    return r;
}

// padded row strides (fp16 elements): rows step 4 banks -> conflict-free ldmatrix
#define S64  72     // rows of 64 fp16
#define S128 136    // rows of 128 fp16

// ============================================================================
// Kernel A (full d, 512 threads): dS^T[d][n] = sum_c V[c][d] * Q[c][n]
//   16 warps: wd = w&7 -> d rows 16wd..16wd+15 ; nh = w>>3 -> n cols nh*32..+31
// grid = 512 (bh*16+k), 512 threads, 2 CTAs/SM (32 warps)
// ============================================================================
#define KA_SMEM ((size_t)(128*S128 + 128*S64)*2)   // 53,248 B

__global__ __launch_bounds__(512, 2) void kA(const float* __restrict__ Q,
                                             const float* __restrict__ V) {
    extern __shared__ __half sm[];
    __half* Vf = sm;                 // [128][S128]
    __half* Qf = Vf + 128 * S128;    // [128][S64]

    const int tid = threadIdx.x, w = tid >> 5, L = tid & 31;
    const int cidx = blockIdx.x;
    const int k = cidx & 15, bh = cidx >> 4;
    const int b = bh >> 3, h = bh & 7;

    const float* Qb = Q + ((size_t)(b * T_ + k * C_) * NH_ + h) * N_;
    const float* Vb = V + (size_t)(b * T_ + k * C_) * D_;

    // Q natural [c][n]
#pragma unroll
    for (int it = 0; it < 4; it++) {
        int idx = tid + it * 512;                 // 2048 float4
        int n4 = idx & 15, c = idx >> 4;
        float4 q = *(const float4*)(Qb + (size_t)c * (NH_ * N_) + n4 * 4);
        *(uint2*)(Qf + c * S64 + n4 * 4) = make_uint2(pk2(q.x, q.y), pk2(q.z, q.w));
    }
    // V natural [c][d]
#pragma unroll
    for (int it = 0; it < 8; it++) {
        int idx = tid + it * 512;                 // 4096 float4
        int d4 = idx & 31, c = idx >> 5;
        float4 v = *(const float4*)(Vb + (size_t)c * D_ + d4 * 4);
        *(uint2*)(Vf + c * S128 + d4 * 4) = make_uint2(pk2(v.x, v.y), pk2(v.z, v.w));
    }
    __syncthreads();

    const int wd = w & 7, nh = w >> 3;
    // A (V^T, m = d rows 16wd..16wd+15) trans x4
    const uint32_t aA = smem_u32(
        Vf + ((L & 7) + ((L >> 4) << 3)) * S128 + 16 * wd + (((L >> 3) & 1) << 3));
    // B (Q^T) trans x4: 16 n-cols per ldmatrix, base col = nh*32
    const uint32_t aB = smem_u32(Qf + (L & 15) * S64 + ((L >> 4) << 3) + nh * 32);

    float acc[4][4];
#pragma unroll
    for (int j = 0; j < 4; j++)
#pragma unroll
        for (int q = 0; q < 4; q++) acc[j][q] = 0.f;

#pragma unroll
    for (int kk = 0; kk < 8; kk++) {
        uint32_t a4[4];
        ldmx4t(a4, aA + kk * (16 * S128 * 2));
#pragma unroll
        for (int jp = 0; jp < 2; jp++) {
            uint32_t br[4];   // {b0(j0), b1(j0), b0(j1), b1(j1)}
            ldmx4t(br, aB + kk * (16 * S64 * 2) + jp * 32);
            mma(acc[2 * jp],     a4, br);
            mma(acc[2 * jp + 1], a4, br + 2);
        }
    }

    const int r0 = 16 * wd + (L >> 2);
    const int cc = nh * 32 + (L & 3) * 2;
    float* op = g_dS + (size_t)cidx * 8192;
#pragma unroll
    for (int j = 0; j < 4; j++) {
        *(float2*)(op + (size_t)r0 * 64 + 8 * j + cc)       = make_float2(acc[j][0], acc[j][1]);
        *(float2*)(op + (size_t)(r0 + 8) * 64 + 8 * j + cc) = make_float2(acc[j][2], acc[j][3]);
    }
}

// ============================================================================
// Kernel B (4-wide): exclusive prefix over the 16 chunks -> fp16 plane + fp32
// new_state.  65536 threads, each owns 4 consecutive n of one (bh,d).
// ============================================================================
__global__ void kB(const float* __restrict__ state, float* __restrict__ out_state) {
    int gid = blockIdx.x * 256 + threadIdx.x;       // < 65536
    int bh = gid >> 11;
    int e4 = (gid & 2047) * 4;
    int d = e4 >> 6, n0 = e4 & 63;
    const size_t base = (size_t)bh * NC_ * 8192 + e4;
    const size_t stb = ((size_t)bh * 64 + n0) * 128 + d;   // state[n][d], n stride 128

    float4 run;
    run.x = state[stb];
    run.y = state[stb + 128];
    run.z = state[stb + 256];
    run.w = state[stb + 384];
#pragma unroll
    for (int k = 0; k < NC_; k++) {
        float4 v = *(const float4*)(g_dS + base + (size_t)k * 8192);
        *(uint2*)(g_spf + base + (size_t)k * 8192) =
            make_uint2(pk2(run.x, run.y), pk2(run.z, run.w));
        run.x += v.x; run.y += v.y; run.z += v.z; run.w += v.w;
    }
    if (out_state) {
        out_state[stb]       = run.x;
        out_state[stb + 128] = run.y;
        out_state[stb + 256] = run.z;
        out_state[stb + 384] = run.w;
    }
}

// ============================================================================
// Kernel C (full-d CTA, dh halves sequential, triangular skip):
//   rb = w<4 ? w : 11-w  (SMSP-balanced row blocks)
//   Phase 1 (ONCE): scores = tril(Q Q^T, -1), u-blocks jp <= rb -> PA frags
//   Per dh in {0,1}:  out = Q @ Spref[:,dh] + scores @ V[:,dh]
// grid = 512 (chunks), 256 threads, 2 CTAs/SM
// ============================================================================
#define KC_SMEM ((size_t)(128*S64 + 128*S64 + 128*S128)*2)   // 71,680 B

__global__ __launch_bounds__(256, 2) void kC(const float* __restrict__ Q,
                                             const float* __restrict__ V,
                                             float* __restrict__ out) {
    extern __shared__ __half sm[];
    __half* Qf = sm;                 // [128][S64]   Q[t][n]
    __half* Sf = Qf + 128 * S64;     // [128][S64]   Spref^T[d][n] (full d)
    __half* Vf = Sf + 128 * S64;     // [128][S128]  V[u][d] (full d)

    const int tid = threadIdx.x, w = tid >> 5, L = tid & 31;
    const int cidx = blockIdx.x;
    const int k = cidx & 15, bh = cidx >> 4;
    const int b = bh >> 3, h = bh & 7;

    const float* Qb = Q + ((size_t)(b * T_ + k * C_) * NH_ + h) * N_;
    const float* Vb = V + (size_t)(b * T_ + k * C_) * D_;

    // Q natural [t][n]
#pragma unroll
    for (int it = 0; it < 8; it++) {
        int idx = tid + it * 256;                 // 2048 float4
        int n4 = idx & 15, t = idx >> 4;
        float4 q = *(const float4*)(Qb + (size_t)t * (NH_ * N_) + n4 * 4);
        *(uint2*)(Qf + t * S64 + n4 * 4) = make_uint2(pk2(q.x, q.y), pk2(q.z, q.w));
    }
    // Spref plane: straight 16B copies of [d][n] fp16 (all 128 d rows)
#pragma unroll
    for (int it = 0; it < 4; it++) {
        int idx = tid + it * 256;                 // 1024 uint4
        int ch = idx & 7, d = idx >> 3;
        size_t sbase = (size_t)cidx * 8192 + (size_t)d * 64 + ch * 8;
        *(uint4*)(Sf + d * S64 + ch * 8) = *(const uint4*)(g_spf + sbase);
    }
    // V natural [u][d]
#pragma unroll
    for (int it = 0; it < 16; it++) {
        int idx = tid + it * 256;                 // 4096 float4
        int d4 = idx & 31, u = idx >> 5;
        float4 v = *(const float4*)(Vb + (size_t)u * D_ + d4 * 4);
        *(uint2*)(Vf + u * S128 + d4 * 4) = make_uint2(pk2(v.x, v.y), pk2(v.z, v.w));
    }
    __syncthreads();

    // SMSP-balanced row-block permutation: pairs (0,7),(1,6),(2,5),(3,4)
    const int rb = (w < 4) ? w : 11 - w;
    const int Lm = L & 15;
    // A (Q rows 16rb..16rb+15) non-trans x4
    const uint32_t aQA = smem_u32(Qf + (16 * rb + Lm) * S64 + ((L >> 4) << 3));
    // B non-trans x4: 2 j-tiles per ldmatrix
    const uint32_t aQB = smem_u32(
        Qf + ((L & 7) + ((L >> 4) << 3)) * S64 + (((L >> 3) & 1) << 3));
    const uint32_t aSB = smem_u32(
        Sf + ((L & 7) + ((L >> 4) << 3)) * S64 + (((L >> 3) & 1) << 3));
    // B (V^T) trans x4: 16 d-cols per ldmatrix
    const uint32_t aVB = smem_u32(Vf + (L & 15) * S128 + ((L >> 4) << 3));

    const int r0 = 16 * rb + (L >> 2);

    // A fragments for all 4 k16 blocks (n = 0..63): reused by phases 1 and 2
    uint32_t Aall[4][4];
#pragma unroll
    for (int kk = 0; kk < 4; kk++) ldmx4(Aall[kk], aQA + kk * 32);

    // ---- Phase 1 (once): scores = tril(Q Q^T, -1); PA[jp]: u = 16jp..16jp+15 ----
    uint32_t PA[8][4];
#pragma unroll
    for (int j = 0; j < 8; j++)
#pragma unroll
        for (int q = 0; q < 4; q++) PA[j][q] = 0u;

#pragma unroll
    for (int jp = 0; jp < 8; jp++) {
        if (jp <= rb) {                           // warp-uniform
            float sc0[4] = {0.f, 0.f, 0.f, 0.f};
            float sc1[4] = {0.f, 0.f, 0.f, 0.f};
#pragma unroll
            for (int kk = 0; kk < 4; kk++) {
                uint32_t br[4];
                ldmx4(br, aQB + jp * (16 * S64 * 2) + kk * 32);
                mma(sc0, Aall[kk], br);
                mma(sc1, Aall[kk], br + 2);
            }
            // strict tril mask + fp16 A-fragment packing
            int u0 = 16 * jp + (L & 3) * 2;
            float x0 = (u0     < r0)     ? sc0[0] : 0.f;
            float x1 = (u0 + 1 < r0)     ? sc0[1] : 0.f;
            float x2 = (u0     < r0 + 8) ? sc0[2] : 0.f;
            float x3 = (u0 + 1 < r0 + 8) ? sc0[3] : 0.f;
            float y0 = (u0 + 8 < r0)     ? sc1[0] : 0.f;
            float y1 = (u0 + 9 < r0)     ? sc1[1] : 0.f;
            float y2 = (u0 + 8 < r0 + 8) ? sc1[2] : 0.f;
            float y3 = (u0 + 9 < r0 + 8) ? sc1[3] : 0.f;
            PA[jp][0] = pk2(x0, x1);
            PA[jp][1] = pk2(x2, x3);
            PA[jp][2] = pk2(y0, y1);
            PA[jp][3] = pk2(y2, y3);
        }
    }

    // ---- Per d-half: out = Q @ Spref + scores @ V ----
    const int tg = b * T_ + k * C_;
#pragma unroll
    for (int dh = 0; dh < 2; dh++) {
        const uint32_t sOff = (uint32_t)dh * (64 * S64 * 2);   // 64 d-rows
        const uint32_t vOff = (uint32_t)dh * 128;              // 64 d-cols (bytes)

        float o[8][4];
#pragma unroll
        for (int j = 0; j < 8; j++)
#pragma unroll
            for (int q = 0; q < 4; q++) o[j][q] = 0.f;

        // Phase 2: out = Q @ Spref_half (K = 64, 8 d-tiles)
#pragma unroll
        for (int kk = 0; kk < 4; kk++) {
#pragma unroll
            for (int jp = 0; jp < 4; jp++) {
                uint32_t br[4];
                ldmx4(br, aSB + sOff + jp * (16 * S64 * 2) + kk * 32);
                mma(o[2 * jp],     Aall[kk], br);
                mma(o[2 * jp + 1], Aall[kk], br + 2);
            }
        }

        // Phase 3: out += scores @ V_half (kk <= rb, unrolled predication)
#pragma unroll
        for (int kk = 0; kk < 8; kk++) {
            if (kk <= rb) {                       // warp-uniform, static PA index
#pragma unroll
                for (int jp = 0; jp < 4; jp++) {
                    uint32_t br[4];
                    ldmx4t(br, aVB + vOff + kk * (16 * S128 * 2) + jp * 32);
                    mma(o[2 * jp],     PA[kk], br);
                    mma(o[2 * jp + 1], PA[kk], br + 2);
                }
            }
        }

        // store out[t][dh*64 + d-local]
#pragma unroll
        for (int j = 0; j < 8; j++) {
            int d0 = dh * 64 + 8 * j + (L & 3) * 2;
            *(float2*)(out + ((size_t)(tg + r0) * NH_ + h) * D_ + d0) =
                make_float2(o[j][0], o[j][1]);
            *(float2*)(out + ((size_t)(tg + r0 + 8) * NH_ + h) * D_ + d0) =
                make_float2(o[j][2], o[j][3]);
        }
    }
}

// ---------------------------------------------------------------------------
extern "C" void kernel_launch(void* const* d_in, const int* in_sizes, int n_in,
                              void* d_out, int out_size) {
    const float* Q     = (const float*)d_in[0];
    const float* V     = (const float*)d_in[1];
    const float* state = (const float*)d_in[2];
    float* out = (float*)d_out;

    cudaFuncSetAttribute(kA, cudaFuncAttributeMaxDynamicSharedMemorySize, (int)KA_SMEM);
    cudaFuncSetAttribute(kC, cudaFuncAttributeMaxDynamicSharedMemorySize, (int)KC_SMEM);

    bool write_state = (out_size >= (OUT_ELEMS + ST_ELEMS));
    float* out_state = write_state ? (out + OUT_ELEMS) : nullptr;

    kA<<<512, 512, KA_SMEM>>>(Q, V);
    kB<<<256, 256>>>(state, out_state);
    kC<<<512, 256, KC_SMEM>>>(Q, V, out);
}

// round 13
// speedup vs baseline: 2.7257x; 1.0626x over previous
#include <cuda_runtime.h>
#include <cuda_fp16.h>
#include <cstdint>

// Problem constants (fixed by the dataset)
#define B_  4
#define T_  2048
#define NH_ 8
#define N_  64
#define D_  128
#define C_  128          // chunk length
#define NC_ 16           // T_/C_
#define OUT_ELEMS (B_*T_*NH_*D_)   // 8,388,608
#define ST_ELEMS  (B_*NH_*N_*D_)   // 262,144

// Scratch:
//  g_dS  : per-chunk delta-state, layout [bh*16+k][d][n] fp32
//  g_spf : prefix state (state + sum_{j<k} dS_j), fp16, [blk][d][n]
__device__ float  g_dS [(size_t)512*8192];
__device__ __half g_spf[(size_t)512*8192];

// ---------------------------------------------------------------------------
// helpers
// ---------------------------------------------------------------------------
__device__ __forceinline__ uint32_t smem_u32(const void* p) {
    uint32_t a;
    asm("{ .reg .u64 t; cvta.to.shared.u64 t, %1; cvt.u32.u64 %0, t; }"
        : "=r"(a) : "l"(p));
    return a;
}
__device__ __forceinline__ void ldmx4(uint32_t* r, uint32_t a) {
    asm volatile("ldmatrix.sync.aligned.m8n8.x4.shared.b16 {%0,%1,%2,%3}, [%4];"
                 : "=r"(r[0]), "=r"(r[1]), "=r"(r[2]), "=r"(r[3]) : "r"(a));
}
__device__ __forceinline__ void ldmx4t(uint32_t* r, uint32_t a) {
    asm volatile("ldmatrix.sync.aligned.m8n8.x4.trans.shared.b16 {%0,%1,%2,%3}, [%4];"
                 : "=r"(r[0]), "=r"(r[1]), "=r"(r[2]), "=r"(r[3]) : "r"(a));
}
// D += A * B, m16n8k16, row.col, fp16 in / fp32 accum
__device__ __forceinline__ void mma(float* d, const uint32_t* a, const uint32_t* b) {
    asm volatile("mma.sync.aligned.m16n8k16.row.col.f32.f16.f16.f32 "
                 "{%0,%1,%2,%3}, {%4,%5,%6,%7}, {%8,%9}, {%0,%1,%2,%3};"
                 : "+f"(d[0]), "+f"(d[1]), "+f"(d[2]), "+f"(d[3])
                 : "r"(a[0]), "r"(a[1]), "r"(a[2]), "r"(a[3]),
                   "r"(b[0]), "r"(b[1]));
}
// pack two fp32 -> fp16x2 (a in low half)
__device__ __forceinline__ uint32_t pk2(float a, float b) {
    uint32_t r;
    asm("cvt.rn.f16x2.f32 %0, %1, %2;" : "=r"(r) : "f"(b), "f"(a));
    return r;
}

// padded row strides (fp16 elements): rows step 4 banks -> conflict-free ldmatrix
#define S64  72     // rows of 64 fp16
#define S128 136    // rows of 128 fp16

// ============================================================================
// Kernel A (2 heads per CTA, V loaded once):
//   dS^T[d][n] = sum_c V[c][d] * Q_h[c][n]  for h = hp*2, hp*2+1
// grid = 256 (b*64 + k*4 + hp), 512 threads, 2 CTAs/SM -> single wave
// ============================================================================
#define KA_SMEM ((size_t)(128*S128 + 128*S64)*2)   // 53,248 B

__global__ __launch_bounds__(512, 2) void kA(const float* __restrict__ Q,
                                             const float* __restrict__ V) {
    extern __shared__ __half sm[];
    __half* Vf = sm;                 // [128][S128]
    __half* Qf = Vf + 128 * S128;    // [128][S64]

    const int tid = threadIdx.x, w = tid >> 5, L = tid & 31;
    const int hp = blockIdx.x & 3, k = (blockIdx.x >> 2) & 15, b = blockIdx.x >> 6;

    const float* Vb = V + (size_t)(b * T_ + k * C_) * D_;

    // V natural [c][d] -- loaded ONCE for both heads
#pragma unroll
    for (int it = 0; it < 8; it++) {
        int idx = tid + it * 512;                 // 4096 float4
        int d4 = idx & 31, c = idx >> 5;
        float4 v = *(const float4*)(Vb + (size_t)c * D_ + d4 * 4);
        *(uint2*)(Vf + c * S128 + d4 * 4) = make_uint2(pk2(v.x, v.y), pk2(v.z, v.w));
    }

    const int wd = w & 7, nh = w >> 3;
    // A (V^T, m = d rows 16wd..16wd+15) trans x4
    const uint32_t aA = smem_u32(
        Vf + ((L & 7) + ((L >> 4) << 3)) * S128 + 16 * wd + (((L >> 3) & 1) << 3));
    // B (Q^T) trans x4: 16 n-cols per ldmatrix, base col = nh*32
    const uint32_t aB = smem_u32(Qf + (L & 15) * S64 + ((L >> 4) << 3) + nh * 32);

    const int r0d = 16 * wd + (L >> 2);
    const int cc = nh * 32 + (L & 3) * 2;

#pragma unroll
    for (int hh = 0; hh < 2; hh++) {
        const int h = hp * 2 + hh;
        const float* Qb = Q + ((size_t)(b * T_ + k * C_) * NH_ + h) * N_;

        // Q natural [c][n]
#pragma unroll
        for (int it = 0; it < 4; it++) {
            int idx = tid + it * 512;             // 2048 float4
            int n4 = idx & 15, c = idx >> 4;
            float4 q = *(const float4*)(Qb + (size_t)c * (NH_ * N_) + n4 * 4);
            *(uint2*)(Qf + c * S64 + n4 * 4) = make_uint2(pk2(q.x, q.y), pk2(q.z, q.w));
        }
        __syncthreads();

        float acc[4][4];
#pragma unroll
        for (int j = 0; j < 4; j++)
#pragma unroll
            for (int q = 0; q < 4; q++) acc[j][q] = 0.f;

#pragma unroll
        for (int kk = 0; kk < 8; kk++) {
            uint32_t a4[4];
            ldmx4t(a4, aA + kk * (16 * S128 * 2));
#pragma unroll
            for (int jp = 0; jp < 2; jp++) {
                uint32_t br[4];
                ldmx4t(br, aB + kk * (16 * S64 * 2) + jp * 32);
                mma(acc[2 * jp],     a4, br);
                mma(acc[2 * jp + 1], a4, br + 2);
            }
        }

        float* op = g_dS + (size_t)((b * NH_ + h) * NC_ + k) * 8192;
#pragma unroll
        for (int j = 0; j < 4; j++) {
            *(float2*)(op + (size_t)r0d * 64 + 8 * j + cc)       = make_float2(acc[j][0], acc[j][1]);
            *(float2*)(op + (size_t)(r0d + 8) * 64 + 8 * j + cc) = make_float2(acc[j][2], acc[j][3]);
        }
        __syncthreads();   // Q buffer reused by next head
    }
}

// ============================================================================
// Kernel B (4-wide): exclusive prefix over the 16 chunks -> fp16 plane + fp32
// new_state.  65536 threads, each owns 4 consecutive n of one (bh,d).
// ============================================================================
__global__ void kB(const float* __restrict__ state, float* __restrict__ out_state) {
    int gid = blockIdx.x * 256 + threadIdx.x;       // < 65536
    int bh = gid >> 11;
    int e4 = (gid & 2047) * 4;
    int d = e4 >> 6, n0 = e4 & 63;
    const size_t base = (size_t)bh * NC_ * 8192 + e4;
    const size_t stb = ((size_t)bh * 64 + n0) * 128 + d;   // state[n][d], n stride 128

    float4 run;
    run.x = state[stb];
    run.y = state[stb + 128];
    run.z = state[stb + 256];
    run.w = state[stb + 384];
#pragma unroll
    for (int k = 0; k < NC_; k++) {
        float4 v = *(const float4*)(g_dS + base + (size_t)k * 8192);
        *(uint2*)(g_spf + base + (size_t)k * 8192) =
            make_uint2(pk2(run.x, run.y), pk2(run.z, run.w));
        run.x += v.x; run.y += v.y; run.z += v.z; run.w += v.w;
    }
    if (out_state) {
        out_state[stb]       = run.x;
        out_state[stb + 128] = run.y;
        out_state[stb + 256] = run.z;
        out_state[stb + 384] = run.w;
    }
}

// ============================================================================
// Kernel C (2 heads per CTA, V loaded once; full-d, dh halves sequential):
//   per head: scores = tril(Q Q^T, -1) once; out = Q @ Spref + scores @ V
//   rb = w<4 ? w : 11-w  (SMSP-balanced row blocks), triangular skip
// grid = 256 (b*64 + k*4 + hp), 256 threads, 2 CTAs/SM -> single wave
// ============================================================================
#define KC_SMEM ((size_t)(128*S64 + 128*S64 + 128*S128)*2)   // 71,680 B

__global__ __launch_bounds__(256, 2) void kC(const float* __restrict__ Q,
                                             const float* __restrict__ V,
                                             float* __restrict__ out) {
    extern __shared__ __half sm[];
    __half* Qf = sm;                 // [128][S64]   Q[t][n]
    __half* Sf = Qf + 128 * S64;     // [128][S64]   Spref^T[d][n] (full d)
    __half* Vf = Sf + 128 * S64;     // [128][S128]  V[u][d] (full d)

    const int tid = threadIdx.x, w = tid >> 5, L = tid & 31;
    const int hp = blockIdx.x & 3, k = (blockIdx.x >> 2) & 15, b = blockIdx.x >> 6;

    const float* Vb = V + (size_t)(b * T_ + k * C_) * D_;

    // V natural [u][d] -- loaded ONCE for both heads
#pragma unroll
    for (int it = 0; it < 16; it++) {
        int idx = tid + it * 256;                 // 4096 float4
        int d4 = idx & 31, u = idx >> 5;
        float4 v = *(const float4*)(Vb + (size_t)u * D_ + d4 * 4);
        *(uint2*)(Vf + u * S128 + d4 * 4) = make_uint2(pk2(v.x, v.y), pk2(v.z, v.w));
    }

    // SMSP-balanced row-block permutation: pairs (0,7),(1,6),(2,5),(3,4)
    const int rb = (w < 4) ? w : 11 - w;
    const int Lm = L & 15;
    const uint32_t aQA = smem_u32(Qf + (16 * rb + Lm) * S64 + ((L >> 4) << 3));
    const uint32_t aQB = smem_u32(
        Qf + ((L & 7) + ((L >> 4) << 3)) * S64 + (((L >> 3) & 1) << 3));
    const uint32_t aSB = smem_u32(
        Sf + ((L & 7) + ((L >> 4) << 3)) * S64 + (((L >> 3) & 1) << 3));
    const uint32_t aVB = smem_u32(Vf + (L & 15) * S128 + ((L >> 4) << 3));

    const int r0 = 16 * rb + (L >> 2);

#pragma unroll
    for (int hh = 0; hh < 2; hh++) {
        const int h = hp * 2 + hh;
        const float* Qb = Q + ((size_t)(b * T_ + k * C_) * NH_ + h) * N_;
        const size_t cidx = (size_t)((b * NH_ + h) * NC_ + k);

        // Q natural [t][n]
#pragma unroll
        for (int it = 0; it < 8; it++) {
            int idx = tid + it * 256;             // 2048 float4
            int n4 = idx & 15, t = idx >> 4;
            float4 q = *(const float4*)(Qb + (size_t)t * (NH_ * N_) + n4 * 4);
            *(uint2*)(Qf + t * S64 + n4 * 4) = make_uint2(pk2(q.x, q.y), pk2(q.z, q.w));
        }
        // Spref plane: straight 16B copies of [d][n] fp16 (all 128 d rows)
#pragma unroll
        for (int it = 0; it < 4; it++) {
            int idx = tid + it * 256;             // 1024 uint4
            int ch = idx & 7, d = idx >> 3;
            size_t sbase = cidx * 8192 + (size_t)d * 64 + ch * 8;
            *(uint4*)(Sf + d * S64 + ch * 8) = *(const uint4*)(g_spf + sbase);
        }
        __syncthreads();

        // A fragments for all 4 k16 blocks (n = 0..63): phases 1 and 2
        uint32_t Aall[4][4];
#pragma unroll
        for (int kk = 0; kk < 4; kk++) ldmx4(Aall[kk], aQA + kk * 32);

        // ---- Phase 1: scores = tril(Q Q^T, -1); PA[jp]: u = 16jp..16jp+15 ----
        uint32_t PA[8][4];
#pragma unroll
        for (int j = 0; j < 8; j++)
#pragma unroll
            for (int q = 0; q < 4; q++) PA[j][q] = 0u;

#pragma unroll
        for (int jp = 0; jp < 8; jp++) {
            if (jp <= rb) {                       // warp-uniform
                float sc0[4] = {0.f, 0.f, 0.f, 0.f};
                float sc1[4] = {0.f, 0.f, 0.f, 0.f};
#pragma unroll
                for (int kk = 0; kk < 4; kk++) {
                    uint32_t br[4];
                    ldmx4(br, aQB + jp * (16 * S64 * 2) + kk * 32);
                    mma(sc0, Aall[kk], br);
                    mma(sc1, Aall[kk], br + 2);
                }
                int u0 = 16 * jp + (L & 3) * 2;
                float x0 = (u0     < r0)     ? sc0[0] : 0.f;
                float x1 = (u0 + 1 < r0)     ? sc0[1] : 0.f;
                float x2 = (u0     < r0 + 8) ? sc0[2] : 0.f;
                float x3 = (u0 + 1 < r0 + 8) ? sc0[3] : 0.f;
                float y0 = (u0 + 8 < r0)     ? sc1[0] : 0.f;
                float y1 = (u0 + 9 < r0)     ? sc1[1] : 0.f;
                float y2 = (u0 + 8 < r0 + 8) ? sc1[2] : 0.f;
                float y3 = (u0 + 9 < r0 + 8) ? sc1[3] : 0.f;
                PA[jp][0] = pk2(x0, x1);
                PA[jp][1] = pk2(x2, x3);
                PA[jp][2] = pk2(y0, y1);
                PA[jp][3] = pk2(y2, y3);
            }
        }

        // ---- Per d-half: out = Q @ Spref + scores @ V ----
        const int tg = b * T_ + k * C_;
#pragma unroll
        for (int dh = 0; dh < 2; dh++) {
            const uint32_t sOff = (uint32_t)dh * (64 * S64 * 2);   // 64 d-rows
            const uint32_t vOff = (uint32_t)dh * 128;              // 64 d-cols (bytes)

            float o[8][4];
#pragma unroll
            for (int j = 0; j < 8; j++)
#pragma unroll
                for (int q = 0; q < 4; q++) o[j][q] = 0.f;

            // Phase 2: out = Q @ Spref_half (K = 64, 8 d-tiles)
#pragma unroll
            for (int kk = 0; kk < 4; kk++) {
#pragma unroll
                for (int jp = 0; jp < 4; jp++) {
                    uint32_t br[4];
                    ldmx4(br, aSB + sOff + jp * (16 * S64 * 2) + kk * 32);
                    mma(o[2 * jp],     Aall[kk], br);
                    mma(o[2 * jp + 1], Aall[kk], br + 2);
                }
            }

            // Phase 3: out += scores @ V_half (kk <= rb, unrolled predication)
#pragma unroll
            for (int kk = 0; kk < 8; kk++) {
                if (kk <= rb) {                   // warp-uniform, static PA index
#pragma unroll
                    for (int jp = 0; jp < 4; jp++) {
                        uint32_t br[4];
                        ldmx4t(br, aVB + vOff + kk * (16 * S128 * 2) + jp * 32);
                        mma(o[2 * jp],     PA[kk], br);
                        mma(o[2 * jp + 1], PA[kk], br + 2);
                    }
                }
            }

            // store out[t][dh*64 + d-local]
#pragma unroll
            for (int j = 0; j < 8; j++) {
                int d0 = dh * 64 + 8 * j + (L & 3) * 2;
                *(float2*)(out + ((size_t)(tg + r0) * NH_ + h) * D_ + d0) =
                    make_float2(o[j][0], o[j][1]);
                *(float2*)(out + ((size_t)(tg + r0 + 8) * NH_ + h) * D_ + d0) =
                    make_float2(o[j][2], o[j][3]);
            }
        }
        __syncthreads();   // Qf/Sf reused by next head
    }
}

// ---------------------------------------------------------------------------
extern "C" void kernel_launch(void* const* d_in, const int* in_sizes, int n_in,
                              void* d_out, int out_size) {
    const float* Q     = (const float*)d_in[0];
    const float* V     = (const float*)d_in[1];
    const float* state = (const float*)d_in[2];
    float* out = (float*)d_out;

    cudaFuncSetAttribute(kA, cudaFuncAttributeMaxDynamicSharedMemorySize, (int)KA_SMEM);
    cudaFuncSetAttribute(kC, cudaFuncAttributeMaxDynamicSharedMemorySize, (int)KC_SMEM);

    bool write_state = (out_size >= (OUT_ELEMS + ST_ELEMS));
    float* out_state = write_state ? (out + OUT_ELEMS) : nullptr;

    kA<<<256, 512, KA_SMEM>>>(Q, V);
    kB<<<256, 256>>>(state, out_state);
    kC<<<256, 256, KC_SMEM>>>(Q, V, out);
}